// round 2
// baseline (speedup 1.0000x reference)
#include <cuda_runtime.h>
#include <stdint.h>

// AddRadiusEdgeIndex: dense [N,N] mask as FLOAT32 (1.0f / 0.0f),
// mask[i,j] = (||p_i - p_j|| <= 3), with EXACTLY the reference's fp32 rounding:
//   sq_i = (x*x + y*y) + z*z                         (plain rn mul/add)
//   dot  = fmaf(z_i,z_j, fmaf(y_i,y_j, x_i*x_j))     (gemm k-loop fma chain)
//   d2   = rn((sq_i + sq_j) - 2*dot)                 (2*dot exact -> fmaf(-2,dot,s) identical)
//   mask = max(d2,0) <= 9  ==  d2 <= 9               (clamp decision-irrelevant, 9 > 0)

#define NPTS 8192
#define JPT  16    // j-points per thread -> 4 float4 stores per (i, thread)
#define TPB  512   // 512 threads * 16 j = full 8192-wide row per block
#define IPB  16    // i-rows per block -> grid = 512 blocks

__global__ __launch_bounds__(TPB, 1)
void radius_mask_kernel(const float* __restrict__ pos, float4* __restrict__ out)
{
    __shared__ float4 si[IPB];   // (x, y, z, sq) for the block's i-rows

    const int t  = threadIdx.x;
    const int i0 = blockIdx.x * IPB;

    if (t < IPB) {
        const int i = i0 + t;
        float x = pos[3 * i + 0];
        float y = pos[3 * i + 1];
        float z = pos[3 * i + 2];
        float sq = __fadd_rn(__fadd_rn(__fmul_rn(x, x), __fmul_rn(y, y)),
                             __fmul_rn(z, z));
        si[t] = make_float4(x, y, z, sq);
    }

    // Each thread owns 16 consecutive j-points, register-resident.
    float xj[JPT], yj[JPT], zj[JPT], sj[JPT];
    const int j0 = t * JPT;
#pragma unroll
    for (int k = 0; k < JPT; k++) {
        const int j = j0 + k;
        float x = pos[3 * j + 0];
        float y = pos[3 * j + 1];
        float z = pos[3 * j + 2];
        xj[k] = x; yj[k] = y; zj[k] = z;
        sj[k] = __fadd_rn(__fadd_rn(__fmul_rn(x, x), __fmul_rn(y, y)),
                          __fmul_rn(z, z));
    }

    __syncthreads();

#pragma unroll 4
    for (int ii = 0; ii < IPB; ii++) {
        const float4 p = si[ii];           // broadcast LDS.128
        float v[JPT];

#pragma unroll
        for (int m = 0; m < JPT; m++) {
            float dot = __fmaf_rn(zj[m], p.z,
                         __fmaf_rn(yj[m], p.y, __fmul_rn(xj[m], p.x)));
            float d2  = __fmaf_rn(-2.0f, dot, __fadd_rn(p.w, sj[m]));
            v[m] = (d2 <= 9.0f) ? 1.0f : 0.0f;
        }

        // 4 coalesced 16B stores: row (i0+ii), cols [t*16, t*16+16)
        float4* row = out + (size_t)(i0 + ii) * (NPTS / 4);
#pragma unroll
        for (int g = 0; g < 4; g++) {
            row[(j0 >> 2) + g] =
                make_float4(v[4 * g + 0], v[4 * g + 1], v[4 * g + 2], v[4 * g + 3]);
        }
    }
}

extern "C" void kernel_launch(void* const* d_in, const int* in_sizes, int n_in,
                              void* d_out, int out_size)
{
    const float* pos = (const float*)d_in[0];
    float4* out = (float4*)d_out;
    radius_mask_kernel<<<NPTS / IPB, TPB>>>(pos, out);
}

// round 3
// speedup vs baseline: 2.3348x; 2.3348x over previous
#include <cuda_runtime.h>
#include <stdint.h>

// AddRadiusEdgeIndex: dense [N,N] float32 mask (1.0f/0.0f),
// mask[i,j] = (||p_i - p_j|| <= 3), reference-exact fp32 rounding:
//   sq  = (x*x + y*y) + z*z                         (plain rn mul/add)
//   dot = fmaf(z_i,z_j, fmaf(y_i,y_j, x_i*x_j))     (gemm k-loop fma chain)
//   d2  = rn((sq_i + sq_j) - 2*dot)                 (fmaf(-2,dot,s): 2*dot exact)
//   mask = d2 <= 9                                  (max(d2,0) clamp irrelevant, 9>0)
//
// R2 -> R3: JPT 16->4, TPB 512->256, IPB 16->32. Regs ~117 -> ~48 so the SM
// holds 5-6 CTAs instead of 1; store latency finally hidden.

#define NPTS 8192
#define JPT  4     // j-points per thread -> one float4 store per i-row
#define TPB  256   // 256 threads * 4 j = 1024 j-cols per block
#define IPB  32    // i-rows per block
// grid = (8192/1024) * (8192/32) = 8 * 256 = 2048 blocks

__global__ __launch_bounds__(TPB)
void radius_mask_kernel(const float* __restrict__ pos, float4* __restrict__ out)
{
    __shared__ float4 si[IPB];   // (x, y, z, sq) for this block's i-rows

    const int t   = threadIdx.x;
    const int jb  = blockIdx.x & 7;          // j-block: 8 per row-stripe
    const int ib  = blockIdx.x >> 3;         // i-stripe: 256 of them
    const int i0  = ib * IPB;
    const int j0  = jb * (TPB * JPT) + t * JPT;

    if (t < IPB) {
        const int i = i0 + t;
        float x = pos[3 * i + 0];
        float y = pos[3 * i + 1];
        float z = pos[3 * i + 2];
        float sq = __fadd_rn(__fadd_rn(__fmul_rn(x, x), __fmul_rn(y, y)),
                             __fmul_rn(z, z));
        si[t] = make_float4(x, y, z, sq);
    }

    // 4 register-resident j-points
    float xj[JPT], yj[JPT], zj[JPT], sj[JPT];
#pragma unroll
    for (int k = 0; k < JPT; k++) {
        const int j = j0 + k;
        float x = pos[3 * j + 0];
        float y = pos[3 * j + 1];
        float z = pos[3 * j + 2];
        xj[k] = x; yj[k] = y; zj[k] = z;
        sj[k] = __fadd_rn(__fadd_rn(__fmul_rn(x, x), __fmul_rn(y, y)),
                          __fmul_rn(z, z));
    }

    __syncthreads();

    const size_t col4 = (size_t)(j0 >> 2);

#pragma unroll 4
    for (int ii = 0; ii < IPB; ii++) {
        const float4 p = si[ii];             // broadcast LDS.128
        float v[JPT];
#pragma unroll
        for (int m = 0; m < JPT; m++) {
            float dot = __fmaf_rn(zj[m], p.z,
                         __fmaf_rn(yj[m], p.y, __fmul_rn(xj[m], p.x)));
            float d2  = __fmaf_rn(-2.0f, dot, __fadd_rn(p.w, sj[m]));
            v[m] = (d2 <= 9.0f) ? 1.0f : 0.0f;
        }
        out[(size_t)(i0 + ii) * (NPTS / 4) + col4] =
            make_float4(v[0], v[1], v[2], v[3]);
    }
}

extern "C" void kernel_launch(void* const* d_in, const int* in_sizes, int n_in,
                              void* d_out, int out_size)
{
    const float* pos = (const float*)d_in[0];
    float4* out = (float4*)d_out;
    radius_mask_kernel<<<(NPTS / (TPB * JPT)) * (NPTS / IPB), TPB>>>(pos, out);
}

// round 4
// speedup vs baseline: 2.3467x; 1.0051x over previous
#include <cuda_runtime.h>
#include <stdint.h>

// AddRadiusEdgeIndex: dense [N,N] float32 mask (1.0f/0.0f),
// mask[i,j] = (||p_i - p_j|| <= 3), reference-exact fp32 rounding:
//   sq  = (x*x + y*y) + z*z                         (plain rn mul/add)
//   dot = fmaf(z_i,z_j, fmaf(y_i,y_j, x_i*x_j))     (gemm k-loop fma chain)
//   d2  = rn((sq_i + sq_j) - 2*dot)                 (fmaf(-2,dot,s): 2*dot exact)
//   mask = d2 <= 9                                  (clamp irrelevant, 9>0)
//
// R3 -> R4: the store stream was issue-paced (5.1 TB/s == issue rate * B/instr).
//  - FSETP+SEL -> FSET.BF via PTX set.le.f32.f32 (7 -> 6 instrs/element)
//  - i-loop unroll 8, strided store pointer (fewer IMADs, more STGs in flight)
//  - __launch_bounds__(256,6) pins 6 CTAs/SM

#define NPTS 8192
#define JPT  4     // j-points per thread -> one float4 store per i-row
#define TPB  256   // 1024 j-cols per block
#define IPB  32    // i-rows per block; grid = 8 * 256 = 2048

__device__ __forceinline__ float set_le(float a, float b)
{
    float r;
    asm("set.le.f32.f32 %0, %1, %2;" : "=f"(r) : "f"(a), "f"(b));
    return r;  // (a <= b) ? 1.0f : 0.0f  -> SASS FSET.BF.LE
}

__global__ __launch_bounds__(TPB, 6)
void radius_mask_kernel(const float* __restrict__ pos, float4* __restrict__ out)
{
    __shared__ float4 si[IPB];   // (x, y, z, sq) for this block's i-rows

    const int t  = threadIdx.x;
    const int jb = blockIdx.x & 7;          // j-block: 8 per row-stripe
    const int ib = blockIdx.x >> 3;         // i-stripe: 256 of them
    const int i0 = ib * IPB;
    const int j0 = jb * (TPB * JPT) + t * JPT;

    if (t < IPB) {
        const int i = i0 + t;
        float x = pos[3 * i + 0];
        float y = pos[3 * i + 1];
        float z = pos[3 * i + 2];
        float sq = __fadd_rn(__fadd_rn(__fmul_rn(x, x), __fmul_rn(y, y)),
                             __fmul_rn(z, z));
        si[t] = make_float4(x, y, z, sq);
    }

    // 4 register-resident j-points
    float xj[JPT], yj[JPT], zj[JPT], sj[JPT];
#pragma unroll
    for (int k = 0; k < JPT; k++) {
        const int j = j0 + k;
        float x = pos[3 * j + 0];
        float y = pos[3 * j + 1];
        float z = pos[3 * j + 2];
        xj[k] = x; yj[k] = y; zj[k] = z;
        sj[k] = __fadd_rn(__fadd_rn(__fmul_rn(x, x), __fmul_rn(y, y)),
                          __fmul_rn(z, z));
    }

    __syncthreads();

    // strided store pointer: one IADD per i-iter instead of IMAD
    float4* dst = out + (size_t)i0 * (NPTS / 4) + (j0 >> 2);

#pragma unroll 8
    for (int ii = 0; ii < IPB; ii++) {
        const float4 p = si[ii];             // broadcast LDS.128
        float v[JPT];
#pragma unroll
        for (int m = 0; m < JPT; m++) {
            float dot = __fmaf_rn(zj[m], p.z,
                         __fmaf_rn(yj[m], p.y, __fmul_rn(xj[m], p.x)));
            float d2  = __fmaf_rn(-2.0f, dot, __fadd_rn(p.w, sj[m]));
            v[m] = set_le(d2, 9.0f);
        }
        *dst = make_float4(v[0], v[1], v[2], v[3]);
        dst += NPTS / 4;
    }
}

extern "C" void kernel_launch(void* const* d_in, const int* in_sizes, int n_in,
                              void* d_out, int out_size)
{
    const float* pos = (const float*)d_in[0];
    float4* out = (float4*)d_out;
    radius_mask_kernel<<<(NPTS / (TPB * JPT)) * (NPTS / IPB), TPB>>>(pos, out);
}

// round 5
// speedup vs baseline: 2.4282x; 1.0347x over previous
#include <cuda_runtime.h>
#include <stdint.h>

// AddRadiusEdgeIndex: dense [N,N] float32 mask (1.0f/0.0f),
// mask[i,j] = (||p_i - p_j|| <= 3), reference-exact fp32 rounding:
//   sq  = (x*x + y*y) + z*z                         (plain rn mul/add)
//   dot = fmaf(z_i,z_j, fmaf(y_i,y_j, x_i*x_j))     (gemm k-loop fma chain)
//   d2  = rn((sq_i + sq_j) - 2*dot)                 (fmaf(-2,dot,s): 2*dot exact)
//   mask = d2 <= 9                                  (clamp irrelevant, 9>0)
//
// R4 -> R5: limiter was CTA wave quantization (2048 CTAs / 888 concurrent =
// 2.31 waves -> ~23% tail idle == the 64% DRAM plateau). IPB 32->16 gives
// 4096 CTAs = 4.61 waves (~8% tail). Output stores use st.global.cs
// (evict-first) to keep the write-once stream from churning L2.

#define NPTS 8192
#define JPT  4     // j-points per thread -> one float4 store per i-row
#define TPB  256   // 1024 j-cols per block
#define IPB  16    // i-rows per block; grid = 8 * 512 = 4096

__device__ __forceinline__ float set_le(float a, float b)
{
    float r;
    asm("set.le.f32.f32 %0, %1, %2;" : "=f"(r) : "f"(a), "f"(b));
    return r;  // (a <= b) ? 1.0f : 0.0f
}

__device__ __forceinline__ void stg_cs_v4(float4* p, float a, float b, float c, float d)
{
    asm volatile("st.global.cs.v4.f32 [%0], {%1, %2, %3, %4};"
                 :: "l"(p), "f"(a), "f"(b), "f"(c), "f"(d) : "memory");
}

__global__ __launch_bounds__(TPB, 6)
void radius_mask_kernel(const float* __restrict__ pos, float4* __restrict__ out)
{
    __shared__ float4 si[IPB];   // (x, y, z, sq) for this block's i-rows

    const int t  = threadIdx.x;
    const int jb = blockIdx.x & 7;          // j-block: 8 per row-stripe
    const int ib = blockIdx.x >> 3;         // i-stripe: 512 of them
    const int i0 = ib * IPB;
    const int j0 = jb * (TPB * JPT) + t * JPT;

    if (t < IPB) {
        const int i = i0 + t;
        float x = pos[3 * i + 0];
        float y = pos[3 * i + 1];
        float z = pos[3 * i + 2];
        float sq = __fadd_rn(__fadd_rn(__fmul_rn(x, x), __fmul_rn(y, y)),
                             __fmul_rn(z, z));
        si[t] = make_float4(x, y, z, sq);
    }

    // 4 register-resident j-points
    float xj[JPT], yj[JPT], zj[JPT], sj[JPT];
#pragma unroll
    for (int k = 0; k < JPT; k++) {
        const int j = j0 + k;
        float x = pos[3 * j + 0];
        float y = pos[3 * j + 1];
        float z = pos[3 * j + 2];
        xj[k] = x; yj[k] = y; zj[k] = z;
        sj[k] = __fadd_rn(__fadd_rn(__fmul_rn(x, x), __fmul_rn(y, y)),
                          __fmul_rn(z, z));
    }

    __syncthreads();

    float4* dst = out + (size_t)i0 * (NPTS / 4) + (j0 >> 2);

#pragma unroll 8
    for (int ii = 0; ii < IPB; ii++) {
        const float4 p = si[ii];             // broadcast LDS.128
        float v[JPT];
#pragma unroll
        for (int m = 0; m < JPT; m++) {
            float dot = __fmaf_rn(zj[m], p.z,
                         __fmaf_rn(yj[m], p.y, __fmul_rn(xj[m], p.x)));
            float d2  = __fmaf_rn(-2.0f, dot, __fadd_rn(p.w, sj[m]));
            v[m] = set_le(d2, 9.0f);
        }
        stg_cs_v4(dst, v[0], v[1], v[2], v[3]);
        dst += NPTS / 4;
    }
}

extern "C" void kernel_launch(void* const* d_in, const int* in_sizes, int n_in,
                              void* d_out, int out_size)
{
    const float* pos = (const float*)d_in[0];
    float4* out = (float4*)d_out;
    radius_mask_kernel<<<(NPTS / (TPB * JPT)) * (NPTS / IPB), TPB>>>(pos, out);
}